// round 1
// baseline (speedup 1.0000x reference)
#include <cuda_runtime.h>
#include <cuda_bf16.h>

#define N_SERIES 2048
#define N_TIME   4096
#define INPUT_SIZE 28
#define OUTPUT_SIZE 7
#define SEAS 7
#define EMB  9
#define S_LEN (N_TIME + SEAS)   /* 4103 */

/* output layout in d_out (flattened tuple concat):
   [0)                windows_y_hat  7*2048*28 = 401408
   [401408)           windows_y      7*2048*7  = 100352  (zeros)
   [501760)           levels         2048*4096 = 8388608
   [8890368)          seasonalities  2048*4103 = 8402944
   total 17293312 */
#define OFF_YHAT 0
#define OFF_YWIN 401408
#define OFF_LEV  501760
#define OFF_SEAS (501760 + N_SERIES * N_TIME)

__global__ void __launch_bounds__(32)
es_recurrence_kernel(const float* __restrict__ y,
                     const int*   __restrict__ idxs,
                     const float* __restrict__ emb,
                     float* __restrict__ L,   /* [N_SERIES][N_TIME] */
                     float* __restrict__ S)   /* [N_SERIES][S_LEN]  */
{
    int s = blockIdx.x * blockDim.x + threadIdx.x;
    if (s >= N_SERIES) return;

    int e = idxs[s];
    const float* ew = emb + (size_t)e * EMB;

    float e0 = ew[0];
    float e1 = ew[1];
    float a   = 1.0f / (1.0f + __expf(-e0));   /* lev_sms  */
    float b   = 1.0f / (1.0f + __expf(-e1));   /* seas_sms */
    float oma = 1.0f - a;
    float omb = 1.0f - b;

    float is[SEAS];
#pragma unroll
    for (int k = 0; k < SEAS; k++) is[k] = __expf(ew[2 + k]);

    const float* yr = y + (size_t)s * N_TIME;
    float*       Lr = L + (size_t)s * N_TIME;
    float*       Sr = S + (size_t)s * S_LEN;

    /* init seasonalities prefix: S[0..6]=init_seas, S[7]=init_seas[0] */
#pragma unroll
    for (int k = 0; k < SEAS; k++) Sr[k] = is[k];
    Sr[SEAS] = is[0];

    float lev = __fdividef(yr[0], is[0]);
    Lr[0] = lev;

    /* ring[j] = season consumed at step (group_base + j);
       group 0 consumes [i1..i6, i0] */
    float ring[SEAS] = { is[1], is[2], is[3], is[4], is[5], is[6], is[0] };

    /* 4095 steps = 585 groups of 7 */
    int t = 1;
#pragma unroll 1
    for (int g = 0; g < (N_TIME - 1) / SEAS; g++) {
#pragma unroll
        for (int j = 0; j < SEAS; j++) {
            float yt = __ldg(yr + t + j);
            float x  = __fdividef(yt, ring[j]);
            lev = fmaf(a, x, oma * lev);
            Lr[t + j] = lev;
            float ns = fmaf(b, __fdividef(yt, lev), omb * ring[j]);
            Sr[t + j + SEAS] = ns;
            ring[j] = ns;
        }
        t += SEAS;
    }
}

__global__ void windows_kernel(const float* __restrict__ y,
                               const float* __restrict__ L,
                               const float* __restrict__ S,
                               float* __restrict__ yhat,   /* [7][2048][28] */
                               float* __restrict__ ywin)   /* [7][2048][7]  */
{
    const int NH = OUTPUT_SIZE * N_SERIES * INPUT_SIZE;   /* 401408 */
    const int NZ = OUTPUT_SIZE * N_SERIES * OUTPUT_SIZE;  /* 100352 */
    int i = blockIdx.x * blockDim.x + threadIdx.x;
    if (i < NH) {
        int ii   = i % INPUT_SIZE;
        int rest = i / INPUT_SIZE;
        int s    = rest % N_SERIES;
        int w    = rest / N_SERIES;
        int start = N_TIME - INPUT_SIZE - OUTPUT_SIZE + 1 + w;  /* 4062+w */
        int t = start + ii;
        float lev = L[(size_t)s * N_TIME + (start + INPUT_SIZE - 1)];
        float se  = S[(size_t)s * S_LEN  + t];
        float yy  = y[(size_t)s * N_TIME + t];
        yhat[i] = logf(yy / (lev * se));
    } else if (i < NH + NZ) {
        ywin[i - NH] = 0.0f;
    }
}

extern "C" void kernel_launch(void* const* d_in, const int* in_sizes, int n_in,
                              void* d_out, int out_size) {
    const float* y    = (const float*)d_in[0];
    const int*   idxs = (const int*)  d_in[1];
    const float* emb  = (const float*)d_in[2];

    float* out  = (float*)d_out;
    float* yhat = out + OFF_YHAT;
    float* ywin = out + OFF_YWIN;
    float* L    = out + OFF_LEV;
    float* S    = out + OFF_SEAS;

    /* 2048 series, 1 thread each; 1 warp per block -> 64 SMs, 1 warp/SMSP */
    es_recurrence_kernel<<<N_SERIES / 32, 32>>>(y, idxs, emb, L, S);

    const int tot = OUTPUT_SIZE * N_SERIES * (INPUT_SIZE + OUTPUT_SIZE); /* 501760 */
    windows_kernel<<<(tot + 255) / 256, 256>>>(y, L, S, yhat, ywin);
}

// round 4
// speedup vs baseline: 3.4418x; 3.4418x over previous
#include <cuda_runtime.h>
#include <cuda_bf16.h>

#define N_SERIES 2048
#define N_TIME   4096
#define INPUT_SIZE 28
#define OUTPUT_SIZE 7
#define SEAS 7
#define EMB  9
#define S_LEN (N_TIME + SEAS)   /* 4103 */

#define OFF_YHAT 0
#define OFF_YWIN 401408
#define OFF_LEV  501760
#define OFF_SEAS (501760 + N_SERIES * N_TIME)

/* 4095 steps = 585 periods of 7. 13 chunks x 315 steps (45 periods).
   Pass A: per chunk, 189-step warmup from phase-aligned guess + 315-step
   body, state only -> boundary state at t=315(c+1) with unknown gauge k_c,
   non-gauge error ~ 0.3 * 0.86^72 ~ 5e-6 (rate HW-measured in R3).
   Pass B: body from handoff state B_{c-1}, measures end level e_c.
   Fixup:  gauge chain k_c = k_{c-1} * B_c.lev / e_c  (k_0 = 1, exact).
   Pass C: body from B_{c-1} with init state gauge-corrected; stores L,S. */
#define NCHUNK 13
#define BODY 315
#define TS   63     /* tile steps */

__device__ float g_lev [NCHUNK][N_SERIES];        /* pass-A end level */
__device__ float g_ring[NCHUNK][SEAS][N_SERIES];  /* pass-A end ring  */
__device__ float g_e   [NCHUNK][N_SERIES];        /* pass-B end level */
__device__ float g_gam [NCHUNK][N_SERIES];        /* gauge per chunk  */

__device__ __forceinline__ void load_params(const int* idxs, const float* emb,
                                            int s, float& a, float& oma,
                                            float& b, float& omb, float* is)
{
    const float* ew = emb + (size_t)idxs[s] * EMB;
    a = 1.0f / (1.0f + __expf(-ew[0]));
    b = 1.0f / (1.0f + __expf(-ew[1]));
    oma = 1.0f - a;
    omb = 1.0f - b;
#pragma unroll
    for (int k = 0; k < SEAS; k++) is[k] = __expf(ew[2 + k]);
}

__device__ __forceinline__ void load_tile(float (*ty)[33], const float* y,
                                          int sg, int tstart, int lane)
{
#pragma unroll 8
    for (int r = 0; r < 32; r++) {
        const float* row = y + (size_t)(sg * 32 + r) * N_TIME + tstart;
        ty[lane][r] = __ldg(row + lane);
        if (lane + 32 < TS) ty[lane + 32][r] = __ldg(row + lane + 32);
    }
}

template<bool STORE>
__device__ __forceinline__ void scan_tile(const float (*ty)[33],
                                          float (*tl)[33], float (*ts)[33],
                                          int lane, float a, float oma,
                                          float b, float omb,
                                          float& lev, float* ring)
{
#pragma unroll
    for (int g = 0; g < TS / SEAS; g++) {
#pragma unroll
        for (int j = 0; j < SEAS; j++) {
            const int toff = g * SEAS + j;
            float yt = ty[toff][lane];
            float x  = __fdividef(yt, ring[j]);
            lev = fmaf(oma, lev, a * x);
            if (STORE) tl[toff][lane] = lev;
            float ns = fmaf(omb, ring[j], b * __fdividef(yt, lev));
            if (STORE) ts[toff][lane] = ns;
            ring[j] = ns;
        }
    }
}

/* ---- Pass A: state propagation from guess (warmup + body, no stores) ---- */
__global__ void __launch_bounds__(32)
passA_kernel(const float* __restrict__ y, const int* __restrict__ idxs,
             const float* __restrict__ emb)
{
    __shared__ float ty[TS][33];
    const int c    = blockIdx.x / 64;
    const int sg   = blockIdx.x % 64;
    const int lane = threadIdx.x;
    const int s    = sg * 32 + lane;

    float a, oma, b, omb, is[SEAS];
    load_params(idxs, emb, s, a, oma, b, omb, is);

    /* chunk 0: exact init at t0=1 (5 tiles). c>0: guess at t0=315c-188
       (8 tiles = 189 warmup + 315 body). t0 == 1 (mod 7) in both cases. */
    const int t0     = (c == 0) ? 1 : (c * BODY - 188);
    const int ntiles = (c == 0) ? 5 : 8;

    float lev = __fdividef(__ldg(y + (size_t)s * N_TIME + (t0 - 1)), is[0]);
    float ring[SEAS] = { is[1], is[2], is[3], is[4], is[5], is[6], is[0] };

    for (int tile = 0; tile < ntiles; tile++) {
        load_tile(ty, y, sg, t0 + tile * TS, lane);
        __syncwarp();
        scan_tile<false>(ty, 0, 0, lane, a, oma, b, omb, lev, ring);
        __syncwarp();
    }
    g_lev[c][s] = lev;
#pragma unroll
    for (int j = 0; j < SEAS; j++) g_ring[c][j][s] = ring[j];
}

/* ---- Pass B: body from handoff state, emit end level ---- */
__global__ void __launch_bounds__(32)
passB_kernel(const float* __restrict__ y, const int* __restrict__ idxs,
             const float* __restrict__ emb)
{
    __shared__ float ty[TS][33];
    const int c    = blockIdx.x / 64 + 1;   /* chunks 1..11 */
    const int sg   = blockIdx.x % 64;
    const int lane = threadIdx.x;
    const int s    = sg * 32 + lane;

    float a, oma, b, omb, is[SEAS];
    load_params(idxs, emb, s, a, oma, b, omb, is);

    float lev = g_lev[c - 1][s];
    float ring[SEAS];
#pragma unroll
    for (int j = 0; j < SEAS; j++) ring[j] = g_ring[c - 1][j][s];

    const int t0 = c * BODY + 1;
    for (int tile = 0; tile < 5; tile++) {
        load_tile(ty, y, sg, t0 + tile * TS, lane);
        __syncwarp();
        scan_tile<false>(ty, 0, 0, lane, a, oma, b, omb, lev, ring);
        __syncwarp();
    }
    g_e[c][s] = lev;
}

/* ---- gauge chain ---- */
__global__ void fixup_kernel()
{
    int s = blockIdx.x * blockDim.x + threadIdx.x;
    if (s >= N_SERIES) return;
    g_gam[0][s] = 1.0f;
    g_gam[1][s] = 1.0f;          /* chunk 1 starts from exact B_0 */
    float kap = 1.0f;
    for (int c = 1; c < NCHUNK - 1; c++) {
        kap *= g_lev[c][s] / g_e[c][s];   /* kappa_c */
        g_gam[c + 1][s] = kap;            /* gauge of chunk c+1 = kappa_c */
    }
}

/* ---- Pass C: body with gauge-corrected init, stores L and S ---- */
__global__ void __launch_bounds__(32)
passC_kernel(const float* __restrict__ y, const int* __restrict__ idxs,
             const float* __restrict__ emb,
             float* __restrict__ L, float* __restrict__ S)
{
    __shared__ float ty[TS][33];
    __shared__ float tl[TS][33];
    __shared__ float ts[TS][33];
    const int c    = blockIdx.x / 64;
    const int sg   = blockIdx.x % 64;
    const int lane = threadIdx.x;
    const int s    = sg * 32 + lane;

    float a, oma, b, omb, is[SEAS];
    load_params(idxs, emb, s, a, oma, b, omb, is);

    float lev, ring[SEAS];
    if (c == 0) {
        lev = __fdividef(__ldg(y + (size_t)s * N_TIME), is[0]);
        ring[0] = is[1]; ring[1] = is[2]; ring[2] = is[3];
        ring[3] = is[4]; ring[4] = is[5]; ring[5] = is[6]; ring[6] = is[0];
        float* Sr = S + (size_t)s * S_LEN;
#pragma unroll
        for (int k = 0; k < SEAS; k++) Sr[k] = is[k];
        Sr[SEAS] = is[0];
        L[(size_t)s * N_TIME] = lev;
    } else {
        float gam  = g_gam[c][s];
        float igam = 1.0f / gam;
        lev = g_lev[c - 1][s] * igam;
#pragma unroll
        for (int j = 0; j < SEAS; j++) ring[j] = g_ring[c - 1][j][s] * gam;
    }

    const int t0  = c * BODY + 1;
    const int to0 = lane, to1 = lane + 32;

    for (int tile = 0; tile < 5; tile++) {
        const int tstart = t0 + tile * TS;
        load_tile(ty, y, sg, tstart, lane);
        __syncwarp();
        scan_tile<true>(ty, tl, ts, lane, a, oma, b, omb, lev, ring);
        __syncwarp();
#pragma unroll 8
        for (int r = 0; r < 32; r++) {
            const size_t lb = (size_t)(sg * 32 + r) * N_TIME + tstart;
            const size_t sb = (size_t)(sg * 32 + r) * S_LEN + tstart + SEAS;
            L[lb + to0] = tl[to0][r];
            S[sb + to0] = ts[to0][r];
            if (to1 < TS) {
                L[lb + to1] = tl[to1][r];
                S[sb + to1] = ts[to1][r];
            }
        }
        __syncwarp();
    }
}

__global__ void windows_kernel(const float* __restrict__ y,
                               const float* __restrict__ L,
                               const float* __restrict__ S,
                               float* __restrict__ yhat,
                               float* __restrict__ ywin)
{
    const int NH = OUTPUT_SIZE * N_SERIES * INPUT_SIZE;   /* 401408 */
    const int NZ = OUTPUT_SIZE * N_SERIES * OUTPUT_SIZE;  /* 100352 */
    int i = blockIdx.x * blockDim.x + threadIdx.x;
    if (i < NH) {
        int ii   = i % INPUT_SIZE;
        int rest = i / INPUT_SIZE;
        int s    = rest % N_SERIES;
        int w    = rest / N_SERIES;
        int start = N_TIME - INPUT_SIZE - OUTPUT_SIZE + 1 + w;
        int t = start + ii;
        float lev = L[(size_t)s * N_TIME + (start + INPUT_SIZE - 1)];
        float se  = S[(size_t)s * S_LEN  + t];
        float yy  = y[(size_t)s * N_TIME + t];
        yhat[i] = logf(yy / (lev * se));
    } else if (i < NH + NZ) {
        ywin[i - NH] = 0.0f;
    }
}

extern "C" void kernel_launch(void* const* d_in, const int* in_sizes, int n_in,
                              void* d_out, int out_size) {
    const float* y    = (const float*)d_in[0];
    const int*   idxs = (const int*)  d_in[1];
    const float* emb  = (const float*)d_in[2];

    float* out  = (float*)d_out;
    float* yhat = out + OFF_YHAT;
    float* ywin = out + OFF_YWIN;
    float* L    = out + OFF_LEV;
    float* S    = out + OFF_SEAS;

    passA_kernel<<<NCHUNK * 64, 32>>>(y, idxs, emb);
    passB_kernel<<<(NCHUNK - 2) * 64, 32>>>(y, idxs, emb);
    fixup_kernel<<<(N_SERIES + 255) / 256, 256>>>();
    passC_kernel<<<NCHUNK * 64, 32>>>(y, idxs, emb, L, S);

    const int tot = OUTPUT_SIZE * N_SERIES * (INPUT_SIZE + OUTPUT_SIZE); /* 501760 */
    windows_kernel<<<(tot + 255) / 256, 256>>>(y, L, S, yhat, ywin);
}